// round 3
// baseline (speedup 1.0000x reference)
#include <cuda_runtime.h>
#include <math.h>
#include <float.h>

#define N 384
#define NPIX (N*N)

// Scratch (no allocations allowed). Scale index: 0->S=5, 1->S=23, 2->S=33.
__device__ float g_plane[3][9][NPIX];   // column-wise top-9, descending in plane idx
__device__ float g_colsum[3][NPIX];
__device__ float g_M[3][NPIX];
__device__ float g_IRIL[3][NPIX];

__device__ __forceinline__ int refl(int i) {
    // jnp 'reflect': -1 -> 1, N -> N-2. Offsets <= 33 < N, one fold suffices.
    if (i < 0) i = -i;
    if (i >= N) i = 2 * N - 2 - i;
    return i;
}

// Ascending top-9 register heap: t[0] = current 9th-largest (min of kept set).
__device__ __forceinline__ void ins9(float (&t)[9], float v) {
    if (v > t[0]) {
        t[0] = v;
#pragma unroll
        for (int i = 0; i < 8; i++) {
            if (t[i] > t[i + 1]) { float tmp = t[i]; t[i] = t[i + 1]; t[i + 1] = tmp; }
            else break;
        }
    }
}

// ---------------------------------------------------------------------------
// K1: fused column pass for all scales. Scan the 33-tall reflected strip in
// order of increasing |dy|, snapshotting top-9 + sum at S=5, 23, 33.
// Planes stored DESCENDING (plane 0 = strip max) for pass-2 early break.
// ---------------------------------------------------------------------------
__global__ void colpass_all(const float* __restrict__ x) {
    int idx = blockIdx.x * blockDim.x + threadIdx.x;
    if (idx >= NPIX) return;
    int iy = idx / N, ix = idx % N;

    float t[9];
#pragma unroll
    for (int i = 0; i < 9; i++) t[i] = -FLT_MAX;
    float sum = 0.0f;

#pragma unroll
    for (int k = 0; k < 33; k++) {
        int mag = (k + 1) >> 1;
        int dy = (k & 1) ? -mag : mag;          // 0,-1,+1,-2,+2,...
        int yy = refl(iy + dy);
        float v = 255.0f * __ldg(&x[yy * N + ix]);
        sum += v;
        ins9(t, v);
        if (k == 4 || k == 22 || k == 32) {
            int s = (k == 4) ? 0 : (k == 22) ? 1 : 2;
#pragma unroll
            for (int p = 0; p < 9; p++) g_plane[s][p][idx] = t[8 - p];
            g_colsum[s][idx] = sum;
        }
    }
}

// ---------------------------------------------------------------------------
// K2: fused row pass. For each scale, merge S sorted-descending column lists
// (reflect cols) with early break; separable box mean from column sums.
// ---------------------------------------------------------------------------
template <int S, int SC>
__device__ __forceinline__ void row_merge(int iy, int ix, int idx) {
    constexpr int P = S / 2;
    float t[9];
#pragma unroll
    for (int i = 0; i < 9; i++) t[i] = -FLT_MAX;
    float sum = 0.0f;

#pragma unroll 4
    for (int dx = -P; dx <= P; dx++) {
        int o = iy * N + refl(ix + dx);
        sum += g_colsum[SC][o];
#pragma unroll
        for (int p = 0; p < 9; p++) {
            float v = g_plane[SC][p][o];
            if (v > t[0]) {
                t[0] = v;
#pragma unroll
                for (int i = 0; i < 8; i++) {
                    if (t[i] > t[i + 1]) { float tmp = t[i]; t[i] = t[i + 1]; t[i + 1] = tmp; }
                    else break;
                }
            } else break;   // list is descending: rest of column can't qualify
        }
    }

    float M = ((t[0] + t[1]) + (t[2] + t[3]) + (t[4] + t[5]) + (t[6] + t[7]) + t[8]) * (1.0f / 9.0f);
    float avg = sum * (1.0f / (float)(S * S));
    g_M[SC][idx] = M;
    g_IRIL[SC][idx] = M - avg;
}

__global__ void rowpass_all() {
    int idx = blockIdx.x * blockDim.x + threadIdx.x;
    if (idx >= NPIX) return;
    int iy = idx / N, ix = idx % N;
    row_merge<5, 0>(iy, ix, idx);
    row_merge<23, 1>(iy, ix, idx);
    row_merge<33, 2>(iy, ix, idx);
}

// ---------------------------------------------------------------------------
// K3: fused combine. Gaussian g inline from x; per scale: BE from M neighbors,
// W from IRIL neighbors; final max over scales (scale-3 branch is exactly 0).
// ---------------------------------------------------------------------------
template <int D, int SC>
__device__ __forceinline__ float combine_one(int iy, int ix, float gg) {
    float BE = -FLT_MAX;
    float ni[9];
#pragma unroll
    for (int i = 0; i < 3; i++) {
        int yy = refl(iy + (i - 1) * D);
#pragma unroll
        for (int j = 0; j < 3; j++) {
            int xx = refl(ix + (j - 1) * D);
            int o = yy * N + xx;
            ni[i * 3 + j] = g_IRIL[SC][o];
            if (!(i == 1 && j == 1)) BE = fmaxf(BE, g_M[SC][o]);
        }
    }

    float SLCM = fmaxf((BE / gg - 1.0f) * gg, 0.0f);

    float WT = ni[4];
    float mx = -FLT_MAX;
    float s = 0.0f;
#pragma unroll
    for (int k = 0; k < 9; k++) {
        if (k == 4) continue;
        mx = fmaxf(mx, ni[k]);
        s += ni[k];
    }
    float mean = s * 0.125f;
    float ss = 0.0f;
#pragma unroll
    for (int k = 0; k < 9; k++) {
        if (k == 4) continue;
        float d = ni[k] - mean;
        ss += d * d;
    }
    float WB = fmaxf(sqrtf(ss * (1.0f / 7.0f)), 5.0f);
    float WD = fmaxf(WT - mx, 0.0f);
    return SLCM * WT * WD / WB;
}

__global__ void combine_all(const float* __restrict__ x, float* __restrict__ out) {
    int idx = blockIdx.x * blockDim.x + threadIdx.x;
    if (idx >= NPIX) return;
    int iy = idx / N, ix = idx % N;

    // g = gaussian3x3(255*x)/16 + 1, reflect pad 1
    const float kw[3] = {1.0f, 2.0f, 1.0f};
    float acc = 0.0f;
#pragma unroll
    for (int dy = -1; dy <= 1; dy++) {
        int yy = refl(iy + dy);
#pragma unroll
        for (int dx = -1; dx <= 1; dx++) {
            int xx = refl(ix + dx);
            acc += kw[dy + 1] * kw[dx + 1] * __ldg(&x[yy * N + xx]);
        }
    }
    float gg = acc * (255.0f / 16.0f) + 1.0f;

    float r = 0.0f;                                 // scale-3 branch is exactly 0
    r = fmaxf(r, combine_one<5, 0>(iy, ix, gg));
    r = fmaxf(r, combine_one<23, 1>(iy, ix, gg));
    r = fmaxf(r, combine_one<33, 2>(iy, ix, gg));
    out[idx] = r;
}

// ---------------------------------------------------------------------------
extern "C" void kernel_launch(void* const* d_in, const int* in_sizes, int n_in,
                              void* d_out, int out_size) {
    const float* x = (const float*)d_in[0];
    float* out = (float*)d_out;

    const int PB = 256, PG = (NPIX + PB - 1) / PB;
    colpass_all<<<PG, PB>>>(x);
    rowpass_all<<<PG, PB>>>();
    combine_all<<<PG, PB>>>(x, out);
}

// round 4
// speedup vs baseline: 1.3475x; 1.3475x over previous
#include <cuda_runtime.h>
#include <math.h>
#include <float.h>

#define N 384
#define NPIX (N*N)

// Scale index: 0->S=5, 1->S=23, 2->S=33.
__device__ float g_p9[3][NPIX][9];     // column top-9, DESCENDING, contiguous per pixel
__device__ float g_colsum[3][NPIX];
__device__ float g_M[3][NPIX];
__device__ float g_IRIL[3][NPIX];

__device__ __forceinline__ int refl(int i) {
    // jnp 'reflect': -1 -> 1, N -> N-2. Offsets <= 33 < N, one fold suffices.
    if (i < 0) i = -i;
    if (i >= N) i = 2 * N - 2 - i;
    return i;
}

// Ascending top-9 register heap: t[0] = current 9th-largest (min of kept set).
__device__ __forceinline__ void ins9(float (&t)[9], float v) {
    if (v > t[0]) {
        t[0] = v;
#pragma unroll
        for (int i = 0; i < 8; i++) {
            if (t[i] > t[i + 1]) { float tmp = t[i]; t[i] = t[i + 1]; t[i + 1] = tmp; }
            else break;
        }
    }
}

// ---------------------------------------------------------------------------
// K1: fused column pass. Scan the 33-tall reflected strip in order of
// increasing |dy|, snapshotting top-9 + sum at S=5, 23, 33.
// ---------------------------------------------------------------------------
__global__ void colpass_all(const float* __restrict__ x) {
    int idx = blockIdx.x * blockDim.x + threadIdx.x;
    if (idx >= NPIX) return;
    int iy = idx / N, ix = idx % N;

    float t[9];
#pragma unroll
    for (int i = 0; i < 9; i++) t[i] = -FLT_MAX;
    float sum = 0.0f;

#pragma unroll
    for (int k = 0; k < 33; k++) {
        int mag = (k + 1) >> 1;
        int dy = (k & 1) ? -mag : mag;          // 0,-1,+1,-2,+2,...
        int yy = refl(iy + dy);
        float v = 255.0f * __ldg(&x[yy * N + ix]);
        sum += v;
        ins9(t, v);
        if (k == 4 || k == 22 || k == 32) {
            int s = (k == 4) ? 0 : (k == 22) ? 1 : 2;
#pragma unroll
            for (int p = 0; p < 9; p++) g_p9[s][idx][p] = t[8 - p];  // descending
            g_colsum[s][idx] = sum;
        }
    }
}

// ---------------------------------------------------------------------------
// K2: row merge from shared memory with warm start.
// Block = 128 consecutive pixels of one row. Stage (128+2P) column lists +
// sums into smem, then: phase A = top-9 of column maxima; phase B = descend
// only columns whose max beats t[0] (provably <= 9 such columns matter).
// ---------------------------------------------------------------------------
#define RP_W 128
#define RP_HALO 16           // max P
#define RP_COLS (RP_W + 2*RP_HALO)

template <int S, int SC>
__device__ __forceinline__ void row_merge_smem(
    float (&s_t9)[RP_COLS][9], float (&s_sum)[RP_COLS],
    int row, int colbase, int tid)
{
    constexpr int P = S / 2;
    constexpr int C = RP_W + 2 * P;

    // Stage column lists (coalesced-ish bulk loads, high MLP).
    const float* src9 = &g_p9[SC][0][0];
    for (int i = tid; i < C * 9; i += RP_W) {
        int c = i / 9, p = i - c * 9;
        int gc = refl(colbase - P + c);
        s_t9[c][p] = __ldg(&src9[(row * N + gc) * 9 + p]);
    }
    for (int i = tid; i < C; i += RP_W) {
        int gc = refl(colbase - P + i);
        s_sum[i] = __ldg(&g_colsum[SC][row * N + gc]);
    }
    __syncthreads();

    float t[9];
#pragma unroll
    for (int i = 0; i < 9; i++) t[i] = -FLT_MAX;

    // Phase A: warm start with the S column maxima.
    for (int j = 0; j < S; j++)
        ins9(t, s_t9[tid + j][0]);

    // Phase B: descend only where the column max still beats t[0].
    for (int j = 0; j < S; j++) {
        if (s_t9[tid + j][0] > t[0]) {
#pragma unroll
            for (int p = 1; p < 9; p++) {
                float v = s_t9[tid + j][p];
                if (v > t[0]) {
                    t[0] = v;
#pragma unroll
                    for (int i = 0; i < 8; i++) {
                        if (t[i] > t[i + 1]) { float tmp = t[i]; t[i] = t[i + 1]; t[i + 1] = tmp; }
                        else break;
                    }
                } else break;    // list descending: rest can't qualify
            }
        }
    }

    float sum = 0.0f;
    for (int j = 0; j < S; j++) sum += s_sum[tid + j];

    float M = ((t[0] + t[1]) + (t[2] + t[3]) + (t[4] + t[5]) + (t[6] + t[7]) + t[8]) * (1.0f / 9.0f);
    float avg = sum * (1.0f / (float)(S * S));
    int idx = row * N + colbase + tid;
    g_M[SC][idx] = M;
    g_IRIL[SC][idx] = M - avg;
    __syncthreads();    // before smem reuse by next scale
}

__global__ void rowpass_all() {
    __shared__ float s_t9[RP_COLS][9];
    __shared__ float s_sum[RP_COLS];
    int row = blockIdx.y;
    int colbase = blockIdx.x * RP_W;
    int tid = threadIdx.x;

    row_merge_smem<5, 0>(s_t9, s_sum, row, colbase, tid);
    row_merge_smem<23, 1>(s_t9, s_sum, row, colbase, tid);
    row_merge_smem<33, 2>(s_t9, s_sum, row, colbase, tid);
}

// ---------------------------------------------------------------------------
// K3: fused combine. Gaussian g inline from x; per scale: BE from M neighbors,
// W from IRIL neighbors; final max over scales (scale-3 branch is exactly 0).
// ---------------------------------------------------------------------------
template <int D, int SC>
__device__ __forceinline__ float combine_one(int iy, int ix, float gg) {
    float BE = -FLT_MAX;
    float ni[9];
#pragma unroll
    for (int i = 0; i < 3; i++) {
        int yy = refl(iy + (i - 1) * D);
#pragma unroll
        for (int j = 0; j < 3; j++) {
            int xx = refl(ix + (j - 1) * D);
            int o = yy * N + xx;
            ni[i * 3 + j] = __ldg(&g_IRIL[SC][o]);
            if (!(i == 1 && j == 1)) BE = fmaxf(BE, __ldg(&g_M[SC][o]));
        }
    }

    float SLCM = fmaxf((BE / gg - 1.0f) * gg, 0.0f);

    float WT = ni[4];
    float mx = -FLT_MAX;
    float s = 0.0f;
#pragma unroll
    for (int k = 0; k < 9; k++) {
        if (k == 4) continue;
        mx = fmaxf(mx, ni[k]);
        s += ni[k];
    }
    float mean = s * 0.125f;
    float ss = 0.0f;
#pragma unroll
    for (int k = 0; k < 9; k++) {
        if (k == 4) continue;
        float d = ni[k] - mean;
        ss += d * d;
    }
    float WB = fmaxf(sqrtf(ss * (1.0f / 7.0f)), 5.0f);
    float WD = fmaxf(WT - mx, 0.0f);
    return SLCM * WT * WD / WB;
}

__global__ void combine_all(const float* __restrict__ x, float* __restrict__ out) {
    int idx = blockIdx.x * blockDim.x + threadIdx.x;
    if (idx >= NPIX) return;
    int iy = idx / N, ix = idx % N;

    // g = gaussian3x3(255*x)/16 + 1, reflect pad 1
    const float kw[3] = {1.0f, 2.0f, 1.0f};
    float acc = 0.0f;
#pragma unroll
    for (int dy = -1; dy <= 1; dy++) {
        int yy = refl(iy + dy);
#pragma unroll
        for (int dx = -1; dx <= 1; dx++) {
            int xx = refl(ix + dx);
            acc += kw[dy + 1] * kw[dx + 1] * __ldg(&x[yy * N + xx]);
        }
    }
    float gg = acc * (255.0f / 16.0f) + 1.0f;

    float r = 0.0f;                                 // scale-3 branch is exactly 0
    r = fmaxf(r, combine_one<5, 0>(iy, ix, gg));
    r = fmaxf(r, combine_one<23, 1>(iy, ix, gg));
    r = fmaxf(r, combine_one<33, 2>(iy, ix, gg));
    out[idx] = r;
}

// ---------------------------------------------------------------------------
extern "C" void kernel_launch(void* const* d_in, const int* in_sizes, int n_in,
                              void* d_out, int out_size) {
    const float* x = (const float*)d_in[0];
    float* out = (float*)d_out;

    const int PB = 256, PG = (NPIX + PB - 1) / PB;
    colpass_all<<<PG, PB>>>(x);

    dim3 rgrid(N / RP_W, N);
    rowpass_all<<<rgrid, RP_W>>>();

    combine_all<<<PG, PB>>>(x, out);
}

// round 5
// speedup vs baseline: 1.3819x; 1.0256x over previous
#include <cuda_runtime.h>
#include <math.h>
#include <float.h>

#define N 384
#define NPIX (N*N)

// Scale index: 0->S=5, 1->S=23, 2->S=33.
// Plane-major: coalesced stores in colpass, coalesced staged reads in rowpass.
__device__ float g_plane[3][9][NPIX];   // descending: plane 0 = column max
__device__ float g_colsum[3][NPIX];
__device__ float g_M[3][NPIX];
__device__ float g_IRIL[3][NPIX];

__device__ __forceinline__ int refl(int i) {
    // jnp 'reflect': -1 -> 1, N -> N-2. Offsets <= 49 < N, one fold suffices.
    if (i < 0) i = -i;
    if (i >= N) i = 2 * N - 2 - i;
    return i;
}

// Ascending top-9 register heap: t[0] = current 9th-largest (min of kept set).
__device__ __forceinline__ void ins9(float (&t)[9], float v) {
    if (v > t[0]) {
        t[0] = v;
#pragma unroll
        for (int i = 0; i < 8; i++) {
            if (t[i] > t[i + 1]) { float tmp = t[i]; t[i] = t[i + 1]; t[i + 1] = tmp; }
            else break;
        }
    }
}

// ---------------------------------------------------------------------------
// K1: fused column pass. Scan the 33-tall reflected strip in order of
// increasing |dy|, snapshotting top-9 + sum at S=5, 23, 33.
// ---------------------------------------------------------------------------
__global__ __launch_bounds__(256) void colpass_all(const float* __restrict__ x) {
    int idx = blockIdx.x * blockDim.x + threadIdx.x;
    if (idx >= NPIX) return;
    int iy = idx / N, ix = idx % N;

    float t[9];
#pragma unroll
    for (int i = 0; i < 9; i++) t[i] = -FLT_MAX;
    float sum = 0.0f;

#pragma unroll
    for (int k = 0; k < 33; k++) {
        int mag = (k + 1) >> 1;
        int dy = (k & 1) ? -mag : mag;          // 0,-1,+1,-2,+2,...
        int yy = refl(iy + dy);
        float v = 255.0f * __ldg(&x[yy * N + ix]);
        sum += v;
        ins9(t, v);
        if (k == 4 || k == 22 || k == 32) {
            int s = (k == 4) ? 0 : (k == 22) ? 1 : 2;
#pragma unroll
            for (int p = 0; p < 9; p++) g_plane[s][p][idx] = t[8 - p];  // descending
            g_colsum[s][idx] = sum;
        }
    }
}

// ---------------------------------------------------------------------------
// K2: row merge from shared memory with warm start.
// Block = 128 consecutive pixels of one row. Stage (128+2P) column lists +
// sums into smem (coalesced per plane), then: phase A = top-9 of column
// maxima; phase B = descend only columns whose max beats t[0].
// ---------------------------------------------------------------------------
#define RP_W 128
#define RP_HALO 16           // max P
#define RP_COLS (RP_W + 2*RP_HALO)

template <int S, int SC>
__device__ __forceinline__ void row_merge_smem(
    float (&s_t9)[RP_COLS][9], float (&s_sum)[RP_COLS],
    int row, int colbase, int tid)
{
    constexpr int P = S / 2;
    constexpr int C = RP_W + 2 * P;

    // Stage: per-plane coalesced global reads -> pixel-major smem (stride 9,
    // conflict-free since gcd(9,32)=1).
#pragma unroll
    for (int p = 0; p < 9; p++) {
        const float* pl = &g_plane[SC][p][row * N];
        for (int i = tid; i < C; i += RP_W)
            s_t9[i][p] = __ldg(&pl[refl(colbase - P + i)]);
    }
    {
        const float* cs = &g_colsum[SC][row * N];
        for (int i = tid; i < C; i += RP_W)
            s_sum[i] = __ldg(&cs[refl(colbase - P + i)]);
    }
    __syncthreads();

    float t[9];
#pragma unroll
    for (int i = 0; i < 9; i++) t[i] = -FLT_MAX;

    // Phase A: warm start with the S column maxima.
    for (int j = 0; j < S; j++)
        ins9(t, s_t9[tid + j][0]);

    // Phase B: descend only where the column max still beats t[0].
    for (int j = 0; j < S; j++) {
        if (s_t9[tid + j][0] > t[0]) {
#pragma unroll
            for (int p = 1; p < 9; p++) {
                float v = s_t9[tid + j][p];
                if (v > t[0]) {
                    t[0] = v;
#pragma unroll
                    for (int i = 0; i < 8; i++) {
                        if (t[i] > t[i + 1]) { float tmp = t[i]; t[i] = t[i + 1]; t[i + 1] = tmp; }
                        else break;
                    }
                } else break;    // list descending: rest can't qualify
            }
        }
    }

    float sum = 0.0f;
    for (int j = 0; j < S; j++) sum += s_sum[tid + j];

    float M = ((t[0] + t[1]) + (t[2] + t[3]) + (t[4] + t[5]) + (t[6] + t[7]) + t[8]) * (1.0f / 9.0f);
    float avg = sum * (1.0f / (float)(S * S));
    int idx = row * N + colbase + tid;
    g_M[SC][idx] = M;
    g_IRIL[SC][idx] = M - avg;
    __syncthreads();    // before smem reuse by next scale
}

__global__ __launch_bounds__(RP_W) void rowpass_all() {
    __shared__ float s_t9[RP_COLS][9];
    __shared__ float s_sum[RP_COLS];
    int row = blockIdx.y;
    int colbase = blockIdx.x * RP_W;
    int tid = threadIdx.x;

    row_merge_smem<5, 0>(s_t9, s_sum, row, colbase, tid);
    row_merge_smem<23, 1>(s_t9, s_sum, row, colbase, tid);
    row_merge_smem<33, 2>(s_t9, s_sum, row, colbase, tid);
}

// ---------------------------------------------------------------------------
// K3: fused combine with smem staging. Block = 128 pixels of one row.
// Per scale: stage 3 rows x (128+2D) of M and IRIL (coalesced), compute
// BE/SLCM/W from smem; final max over scales (scale-3 branch is exactly 0).
// ---------------------------------------------------------------------------
#define CB_W 128
#define CB_MAXC (CB_W + 2*33)

template <int D, int SC>
__device__ __forceinline__ float combine_one_smem(
    float (&sM)[3][CB_MAXC], float (&sI)[3][CB_MAXC],
    int row, int colbase, int tid, float gg)
{
    constexpr int C = CB_W + 2 * D;
    int rows[3] = { refl(row - D), row, refl(row + D) };

#pragma unroll
    for (int k = 0; k < 3; k++) {
        const float* pM = &g_M[SC][rows[k] * N];
        const float* pI = &g_IRIL[SC][rows[k] * N];
        for (int i = tid; i < C; i += CB_W) {
            int gc = refl(colbase - D + i);
            sM[k][i] = __ldg(&pM[gc]);
            sI[k][i] = __ldg(&pI[gc]);
        }
    }
    __syncthreads();

    float BE = -FLT_MAX;
    float ni[9];
#pragma unroll
    for (int k = 0; k < 3; k++) {
#pragma unroll
        for (int j = 0; j < 3; j++) {
            int c = tid + j * D;
            ni[k * 3 + j] = sI[k][c];
            if (!(k == 1 && j == 1)) BE = fmaxf(BE, sM[k][c]);
        }
    }

    float SLCM = fmaxf((BE / gg - 1.0f) * gg, 0.0f);

    float WT = ni[4];
    float mx = -FLT_MAX;
    float s = 0.0f;
#pragma unroll
    for (int k = 0; k < 9; k++) {
        if (k == 4) continue;
        mx = fmaxf(mx, ni[k]);
        s += ni[k];
    }
    float mean = s * 0.125f;
    float ss = 0.0f;
#pragma unroll
    for (int k = 0; k < 9; k++) {
        if (k == 4) continue;
        float d = ni[k] - mean;
        ss += d * d;
    }
    float WB = fmaxf(sqrtf(ss * (1.0f / 7.0f)), 5.0f);
    float WD = fmaxf(WT - mx, 0.0f);
    float r = SLCM * WT * WD / WB;
    __syncthreads();    // before smem reuse by next scale
    return r;
}

__global__ __launch_bounds__(CB_W) void combine_all(const float* __restrict__ x,
                                                    float* __restrict__ out) {
    __shared__ float sM[3][CB_MAXC];
    __shared__ float sI[3][CB_MAXC];
    int row = blockIdx.y;
    int colbase = blockIdx.x * CB_W;
    int tid = threadIdx.x;
    int ix = colbase + tid;

    // g = gaussian3x3(255*x)/16 + 1, reflect pad 1 (x is L1/L2-resident)
    const float kw[3] = {1.0f, 2.0f, 1.0f};
    float acc = 0.0f;
#pragma unroll
    for (int dy = -1; dy <= 1; dy++) {
        int yy = refl(row + dy);
#pragma unroll
        for (int dx = -1; dx <= 1; dx++) {
            int xx = refl(ix + dx);
            acc += kw[dy + 1] * kw[dx + 1] * __ldg(&x[yy * N + xx]);
        }
    }
    float gg = acc * (255.0f / 16.0f) + 1.0f;

    float r = 0.0f;                                 // scale-3 branch is exactly 0
    r = fmaxf(r, combine_one_smem<5, 0>(sM, sI, row, colbase, tid, gg));
    r = fmaxf(r, combine_one_smem<23, 1>(sM, sI, row, colbase, tid, gg));
    r = fmaxf(r, combine_one_smem<33, 2>(sM, sI, row, colbase, tid, gg));
    out[row * N + ix] = r;
}

// ---------------------------------------------------------------------------
extern "C" void kernel_launch(void* const* d_in, const int* in_sizes, int n_in,
                              void* d_out, int out_size) {
    const float* x = (const float*)d_in[0];
    float* out = (float*)d_out;

    colpass_all<<<(NPIX + 255) / 256, 256>>>(x);

    dim3 rgrid(N / RP_W, N);
    rowpass_all<<<rgrid, RP_W>>>();

    dim3 cgrid(N / CB_W, N);
    combine_all<<<cgrid, CB_W>>>(x, out);
}

// round 7
// speedup vs baseline: 2.2419x; 1.6223x over previous
#include <cuda_runtime.h>
#include <math.h>
#include <float.h>

#define N 384
#define NPIX (N*N)

// Scale index: 0->S=5, 1->S=23, 2->S=33.  Plane-major (coalesced).
__device__ float g_plane[3][9][NPIX];   // descending: plane 0 = column max
__device__ float g_colsum[3][NPIX];
__device__ float g_M[3][NPIX];
__device__ float g_IRIL[3][NPIX];

__device__ __forceinline__ int refl(int i) {
    if (i < 0) i = -i;
    if (i >= N) i = 2 * N - 2 - i;
    return i;
}

// Branch-free insert into ascending 9-array (t[0] = min of kept set).
// Inserting v <= t[0] is a no-op; no guard needed.
__device__ __forceinline__ void ins9_bf(float (&t)[9], float v) {
    t[0] = fmaxf(t[0], v);
#pragma unroll
    for (int i = 0; i < 8; i++) {
        float lo = fminf(t[i], t[i + 1]);
        float hi = fmaxf(t[i], t[i + 1]);
        t[i] = lo; t[i + 1] = hi;
    }
}

// ---------------------------------------------------------------------------
// K1: fused column pass, branch-free inserts. Scan 33-tall reflected strip in
// order of increasing |dy|, snapshotting top-9 + sum at S=5, 23, 33.
// ---------------------------------------------------------------------------
__global__ __launch_bounds__(256) void colpass_all(const float* __restrict__ x) {
    int idx = blockIdx.x * blockDim.x + threadIdx.x;
    if (idx >= NPIX) return;
    int iy = idx / N, ix = idx % N;

    float t[9];
#pragma unroll
    for (int i = 0; i < 9; i++) t[i] = -FLT_MAX;
    float sum = 0.0f;

#pragma unroll
    for (int k = 0; k < 33; k++) {
        int mag = (k + 1) >> 1;
        int dy = (k & 1) ? -mag : mag;          // 0,-1,+1,-2,+2,...
        int yy = refl(iy + dy);
        float v = 255.0f * __ldg(&x[yy * N + ix]);
        sum += v;
        ins9_bf(t, v);
        if (k == 4 || k == 22 || k == 32) {
            int s = (k == 4) ? 0 : (k == 22) ? 1 : 2;
#pragma unroll
            for (int p = 0; p < 9; p++) g_plane[s][p][idx] = t[8 - p];  // descending
            g_colsum[s][idx] = sum;
        }
    }
}

// ---------------------------------------------------------------------------
// K2: row merge, branch-free + warp-uniform early break.
// Block = 128 pixels of one row, one scale (blockIdx.z).
// ---------------------------------------------------------------------------
#define RP_W 128
#define RP_HALO 16
#define RP_COLS (RP_W + 2*RP_HALO)

template <int S, int SC>
__device__ __forceinline__ void row_merge_smem(
    float (&s_t9)[RP_COLS][9], float (&s_sum)[RP_COLS],
    int row, int colbase, int tid)
{
    constexpr int P = S / 2;
    constexpr int C = RP_W + 2 * P;

    // Stage: per-plane coalesced global reads -> pixel-major smem
    // (stride 9: gcd(9,32)=1 -> conflict-free).
#pragma unroll
    for (int p = 0; p < 9; p++) {
        const float* pl = &g_plane[SC][p][row * N];
        for (int i = tid; i < C; i += RP_W)
            s_t9[i][p] = __ldg(&pl[refl(colbase - P + i)]);
    }
    {
        const float* cs = &g_colsum[SC][row * N];
        for (int i = tid; i < C; i += RP_W)
            s_sum[i] = __ldg(&cs[refl(colbase - P + i)]);
    }
    __syncthreads();

    float t[9];
#pragma unroll
    for (int i = 0; i < 9; i++) t[i] = -FLT_MAX;

    // Phase A: warm start with the S column maxima (branch-free).
    float sum = 0.0f;
    for (int j = 0; j < S; j++) {
        ins9_bf(t, s_t9[tid + j][0]);
        sum += s_sum[tid + j];
    }

    // Phase B: descend columns.
    if (S == 5) {
        // Small scale: unconditional full descent, zero branches.
        // (45 total elements; inserts of v <= t[0] are no-ops.)
#pragma unroll
        for (int j = 0; j < S; j++)
#pragma unroll
            for (int p = 1; p < 9; p++)
                ins9_bf(t, s_t9[tid + j][p]);
    } else {
        // Large scales: per column, descend while any lane is alive
        // (warp-uniform ballot break; dead lanes' inserts are no-ops).
        for (int j = 0; j < S; j++) {
            bool alive = s_t9[tid + j][0] > t[0];
#pragma unroll
            for (int p = 1; p < 9; p++) {
                if (!__any_sync(0xffffffffu, alive)) break;
                float v = s_t9[tid + j][p];
                ins9_bf(t, v);
                alive = v > t[0];
            }
        }
    }

    float M = ((t[0] + t[1]) + (t[2] + t[3]) + (t[4] + t[5]) + (t[6] + t[7]) + t[8]) * (1.0f / 9.0f);
    float avg = sum * (1.0f / (float)(S * S));
    int idx = row * N + colbase + tid;
    g_M[SC][idx] = M;
    g_IRIL[SC][idx] = M - avg;
}

__global__ __launch_bounds__(RP_W) void rowpass_all() {
    __shared__ float s_t9[RP_COLS][9];
    __shared__ float s_sum[RP_COLS];
    int row = blockIdx.y;
    int colbase = blockIdx.x * RP_W;
    int tid = threadIdx.x;

    if      (blockIdx.z == 0) row_merge_smem<5, 0>(s_t9, s_sum, row, colbase, tid);
    else if (blockIdx.z == 1) row_merge_smem<23, 1>(s_t9, s_sum, row, colbase, tid);
    else                      row_merge_smem<33, 2>(s_t9, s_sum, row, colbase, tid);
}

// ---------------------------------------------------------------------------
// K3: fused combine (direct loads — R3 form, which measured fastest).
// ---------------------------------------------------------------------------
template <int D, int SC>
__device__ __forceinline__ float combine_one(int iy, int ix, float gg) {
    float BE = -FLT_MAX;
    float ni[9];
#pragma unroll
    for (int i = 0; i < 3; i++) {
        int yy = refl(iy + (i - 1) * D);
#pragma unroll
        for (int j = 0; j < 3; j++) {
            int xx = refl(ix + (j - 1) * D);
            int o = yy * N + xx;
            ni[i * 3 + j] = __ldg(&g_IRIL[SC][o]);
            if (!(i == 1 && j == 1)) BE = fmaxf(BE, __ldg(&g_M[SC][o]));
        }
    }

    float SLCM = fmaxf((BE / gg - 1.0f) * gg, 0.0f);

    float WT = ni[4];
    float mx = -FLT_MAX;
    float s = 0.0f;
#pragma unroll
    for (int k = 0; k < 9; k++) {
        if (k == 4) continue;
        mx = fmaxf(mx, ni[k]);
        s += ni[k];
    }
    float mean = s * 0.125f;
    float ss = 0.0f;
#pragma unroll
    for (int k = 0; k < 9; k++) {
        if (k == 4) continue;
        float d = ni[k] - mean;
        ss += d * d;
    }
    float WB = fmaxf(sqrtf(ss * (1.0f / 7.0f)), 5.0f);
    float WD = fmaxf(WT - mx, 0.0f);
    return SLCM * WT * WD / WB;
}

__global__ __launch_bounds__(256) void combine_all(const float* __restrict__ x,
                                                   float* __restrict__ out) {
    int idx = blockIdx.x * blockDim.x + threadIdx.x;
    if (idx >= NPIX) return;
    int iy = idx / N, ix = idx % N;

    const float kw[3] = {1.0f, 2.0f, 1.0f};
    float acc = 0.0f;
#pragma unroll
    for (int dy = -1; dy <= 1; dy++) {
        int yy = refl(iy + dy);
#pragma unroll
        for (int dx = -1; dx <= 1; dx++) {
            int xx = refl(ix + dx);
            acc += kw[dy + 1] * kw[dx + 1] * __ldg(&x[yy * N + xx]);
        }
    }
    float gg = acc * (255.0f / 16.0f) + 1.0f;

    float r = 0.0f;                                 // scale-3 branch is exactly 0
    r = fmaxf(r, combine_one<5, 0>(iy, ix, gg));
    r = fmaxf(r, combine_one<23, 1>(iy, ix, gg));
    r = fmaxf(r, combine_one<33, 2>(iy, ix, gg));
    out[idx] = r;
}

// ---------------------------------------------------------------------------
extern "C" void kernel_launch(void* const* d_in, const int* in_sizes, int n_in,
                              void* d_out, int out_size) {
    const float* x = (const float*)d_in[0];
    float* out = (float*)d_out;

    colpass_all<<<(NPIX + 255) / 256, 256>>>(x);

    dim3 rgrid(N / RP_W, N, 3);
    rowpass_all<<<rgrid, RP_W>>>();

    combine_all<<<(NPIX + 255) / 256, 256>>>(x, out);
}

// round 8
// speedup vs baseline: 2.2431x; 1.0005x over previous
#include <cuda_runtime.h>
#include <math.h>
#include <float.h>

#define N 384
#define NPIX (N*N)

// Scale index: 0->S=5, 1->S=23, 2->S=33.  Plane-major (coalesced).
__device__ float g_plane[3][9][NPIX];   // descending: plane 0 = column max
__device__ float g_colsum[3][NPIX];
__device__ float g_M[3][NPIX];
__device__ float g_IRIL[3][NPIX];

__device__ __forceinline__ int refl(int i) {
    if (i < 0) i = -i;
    if (i >= N) i = 2 * N - 2 - i;
    return i;
}

// Depth-2 branch-free insert into ascending 9-array (t[0] = min of kept set).
// u = max(v, t[0]) is the surviving new element; result is the sorted merge of
// u into t[1..8]. Each output depends only on u and old t -> ILP-friendly.
// Inserting v <= t[0] is exactly a no-op.
__device__ __forceinline__ void ins9_bf(float (&t)[9], float v) {
    float u  = fmaxf(v, t[0]);
    float r0 = fminf(u, t[1]);
    float r1 = fminf(fmaxf(u, t[1]), t[2]);
    float r2 = fminf(fmaxf(u, t[2]), t[3]);
    float r3 = fminf(fmaxf(u, t[3]), t[4]);
    float r4 = fminf(fmaxf(u, t[4]), t[5]);
    float r5 = fminf(fmaxf(u, t[5]), t[6]);
    float r6 = fminf(fmaxf(u, t[6]), t[7]);
    float r7 = fminf(fmaxf(u, t[7]), t[8]);
    float r8 = fmaxf(u, t[8]);
    t[0] = r0; t[1] = r1; t[2] = r2; t[3] = r3; t[4] = r4;
    t[5] = r5; t[6] = r6; t[7] = r7; t[8] = r8;
}

// ---------------------------------------------------------------------------
// K1: fused column pass. Scan 33-tall reflected strip in order of increasing
// |dy|, snapshotting top-9 + sum at S=5, 23, 33.
// ---------------------------------------------------------------------------
__global__ __launch_bounds__(256) void colpass_all(const float* __restrict__ x) {
    int idx = blockIdx.x * blockDim.x + threadIdx.x;
    if (idx >= NPIX) return;
    int iy = idx / N, ix = idx % N;

    float t[9];
#pragma unroll
    for (int i = 0; i < 9; i++) t[i] = -FLT_MAX;
    float sum = 0.0f;

#pragma unroll
    for (int k = 0; k < 33; k++) {
        int mag = (k + 1) >> 1;
        int dy = (k & 1) ? -mag : mag;          // 0,-1,+1,-2,+2,...
        int yy = refl(iy + dy);
        float v = 255.0f * __ldg(&x[yy * N + ix]);
        sum += v;
        ins9_bf(t, v);
        if (k == 4 || k == 22 || k == 32) {
            int s = (k == 4) ? 0 : (k == 22) ? 1 : 2;
#pragma unroll
            for (int p = 0; p < 9; p++) g_plane[s][p][idx] = t[8 - p];  // descending
            g_colsum[s][idx] = sum;
        }
    }
}

// ---------------------------------------------------------------------------
// K2: row merge, branch-free + warp-uniform early break.
// Block = 128 pixels of one row, one scale (blockIdx.z).
// ---------------------------------------------------------------------------
#define RP_W 128
#define RP_HALO 16
#define RP_COLS (RP_W + 2*RP_HALO)

template <int S, int SC>
__device__ __forceinline__ void row_merge_smem(
    float (&s_t9)[RP_COLS][9], float (&s_sum)[RP_COLS],
    int row, int colbase, int tid)
{
    constexpr int P = S / 2;
    constexpr int C = RP_W + 2 * P;

    // Stage: per-plane coalesced global reads -> pixel-major smem
    // (stride 9: gcd(9,32)=1 -> conflict-free).
#pragma unroll
    for (int p = 0; p < 9; p++) {
        const float* pl = &g_plane[SC][p][row * N];
        for (int i = tid; i < C; i += RP_W)
            s_t9[i][p] = __ldg(&pl[refl(colbase - P + i)]);
    }
    {
        const float* cs = &g_colsum[SC][row * N];
        for (int i = tid; i < C; i += RP_W)
            s_sum[i] = __ldg(&cs[refl(colbase - P + i)]);
    }
    __syncthreads();

    float t[9];
#pragma unroll
    for (int i = 0; i < 9; i++) t[i] = -FLT_MAX;

    // Phase A: warm start with the S column maxima (branch-free).
    float sum = 0.0f;
    for (int j = 0; j < S; j++) {
        ins9_bf(t, s_t9[tid + j][0]);
        sum += s_sum[tid + j];
    }

    // Phase B: descend columns.
    if (S == 5) {
        // Small scale: unconditional full descent, zero branches.
#pragma unroll
        for (int j = 0; j < S; j++)
#pragma unroll
            for (int p = 1; p < 9; p++)
                ins9_bf(t, s_t9[tid + j][p]);
    } else {
        // Large scales: per column, descend while any lane is alive
        // (warp-uniform ballot break; dead lanes' inserts are no-ops).
        for (int j = 0; j < S; j++) {
            bool alive = s_t9[tid + j][0] > t[0];
#pragma unroll
            for (int p = 1; p < 9; p++) {
                if (!__any_sync(0xffffffffu, alive)) break;
                float v = s_t9[tid + j][p];
                ins9_bf(t, v);
                alive = v > t[0];
            }
        }
    }

    float M = ((t[0] + t[1]) + (t[2] + t[3]) + (t[4] + t[5]) + (t[6] + t[7]) + t[8]) * (1.0f / 9.0f);
    float avg = sum * (1.0f / (float)(S * S));
    int idx = row * N + colbase + tid;
    g_M[SC][idx] = M;
    g_IRIL[SC][idx] = M - avg;
}

__global__ __launch_bounds__(RP_W) void rowpass_all() {
    __shared__ float s_t9[RP_COLS][9];
    __shared__ float s_sum[RP_COLS];
    int row = blockIdx.y;
    int colbase = blockIdx.x * RP_W;
    int tid = threadIdx.x;

    if      (blockIdx.z == 0) row_merge_smem<5, 0>(s_t9, s_sum, row, colbase, tid);
    else if (blockIdx.z == 1) row_merge_smem<23, 1>(s_t9, s_sum, row, colbase, tid);
    else                      row_merge_smem<33, 2>(s_t9, s_sum, row, colbase, tid);
}

// ---------------------------------------------------------------------------
// K3: fused combine (direct loads — measured fastest form).
// ---------------------------------------------------------------------------
template <int D, int SC>
__device__ __forceinline__ float combine_one(int iy, int ix, float gg) {
    float BE = -FLT_MAX;
    float ni[9];
#pragma unroll
    for (int i = 0; i < 3; i++) {
        int yy = refl(iy + (i - 1) * D);
#pragma unroll
        for (int j = 0; j < 3; j++) {
            int xx = refl(ix + (j - 1) * D);
            int o = yy * N + xx;
            ni[i * 3 + j] = __ldg(&g_IRIL[SC][o]);
            if (!(i == 1 && j == 1)) BE = fmaxf(BE, __ldg(&g_M[SC][o]));
        }
    }

    float SLCM = fmaxf((BE / gg - 1.0f) * gg, 0.0f);

    float WT = ni[4];
    float mx = -FLT_MAX;
    float s = 0.0f;
#pragma unroll
    for (int k = 0; k < 9; k++) {
        if (k == 4) continue;
        mx = fmaxf(mx, ni[k]);
        s += ni[k];
    }
    float mean = s * 0.125f;
    float ss = 0.0f;
#pragma unroll
    for (int k = 0; k < 9; k++) {
        if (k == 4) continue;
        float d = ni[k] - mean;
        ss += d * d;
    }
    float WB = fmaxf(sqrtf(ss * (1.0f / 7.0f)), 5.0f);
    float WD = fmaxf(WT - mx, 0.0f);
    return SLCM * WT * WD / WB;
}

__global__ __launch_bounds__(256) void combine_all(const float* __restrict__ x,
                                                   float* __restrict__ out) {
    int idx = blockIdx.x * blockDim.x + threadIdx.x;
    if (idx >= NPIX) return;
    int iy = idx / N, ix = idx % N;

    const float kw[3] = {1.0f, 2.0f, 1.0f};
    float acc = 0.0f;
#pragma unroll
    for (int dy = -1; dy <= 1; dy++) {
        int yy = refl(iy + dy);
#pragma unroll
        for (int dx = -1; dx <= 1; dx++) {
            int xx = refl(ix + dx);
            acc += kw[dy + 1] * kw[dx + 1] * __ldg(&x[yy * N + xx]);
        }
    }
    float gg = acc * (255.0f / 16.0f) + 1.0f;

    float r = 0.0f;                                 // scale-3 branch is exactly 0
    r = fmaxf(r, combine_one<5, 0>(iy, ix, gg));
    r = fmaxf(r, combine_one<23, 1>(iy, ix, gg));
    r = fmaxf(r, combine_one<33, 2>(iy, ix, gg));
    out[idx] = r;
}

// ---------------------------------------------------------------------------
extern "C" void kernel_launch(void* const* d_in, const int* in_sizes, int n_in,
                              void* d_out, int out_size) {
    const float* x = (const float*)d_in[0];
    float* out = (float*)d_out;

    colpass_all<<<(NPIX + 255) / 256, 256>>>(x);

    dim3 rgrid(N / RP_W, N, 3);
    rowpass_all<<<rgrid, RP_W>>>();

    combine_all<<<(NPIX + 255) / 256, 256>>>(x, out);
}

// round 9
// speedup vs baseline: 2.7090x; 1.2077x over previous
#include <cuda_runtime.h>
#include <math.h>
#include <float.h>

#define N 384
#define NPIX (N*N)

// Scale index: 0->S=5, 1->S=23, 2->S=33.  Plane-major (coalesced).
__device__ float g_plane[3][9][NPIX];   // descending: plane 0 = column max
__device__ float g_colsum[3][NPIX];
__device__ float g_M[3][NPIX];
__device__ float g_IRIL[3][NPIX];

__device__ __forceinline__ int refl(int i) {
    if (i < 0) i = -i;
    if (i >= N) i = 2 * N - 2 - i;
    return i;
}

// Depth-2 branch-free insert into ascending 9-array (t[0] = min of kept set).
__device__ __forceinline__ void ins9_bf(float (&t)[9], float v) {
    float u  = fmaxf(v, t[0]);
    float r0 = fminf(u, t[1]);
    float r1 = fminf(fmaxf(u, t[1]), t[2]);
    float r2 = fminf(fmaxf(u, t[2]), t[3]);
    float r3 = fminf(fmaxf(u, t[3]), t[4]);
    float r4 = fminf(fmaxf(u, t[4]), t[5]);
    float r5 = fminf(fmaxf(u, t[5]), t[6]);
    float r6 = fminf(fmaxf(u, t[6]), t[7]);
    float r7 = fminf(fmaxf(u, t[7]), t[8]);
    float r8 = fmaxf(u, t[8]);
    t[0] = r0; t[1] = r1; t[2] = r2; t[3] = r3; t[4] = r4;
    t[5] = r5; t[6] = r6; t[7] = r7; t[8] = r8;
}

// ---------------------------------------------------------------------------
// K1: fused column pass (unchanged — measured 10us). Scan 33-tall reflected
// strip in order of increasing |dy|, snapshot top-9 + sum at S=5, 23, 33.
// ---------------------------------------------------------------------------
__global__ __launch_bounds__(256) void colpass_all(const float* __restrict__ x) {
    int idx = blockIdx.x * blockDim.x + threadIdx.x;
    if (idx >= NPIX) return;
    int iy = idx / N, ix = idx % N;

    float t[9];
#pragma unroll
    for (int i = 0; i < 9; i++) t[i] = -FLT_MAX;
    float sum = 0.0f;

#pragma unroll
    for (int k = 0; k < 33; k++) {
        int mag = (k + 1) >> 1;
        int dy = (k & 1) ? -mag : mag;          // 0,-1,+1,-2,+2,...
        int yy = refl(iy + dy);
        float v = 255.0f * __ldg(&x[yy * N + ix]);
        sum += v;
        ins9_bf(t, v);
        if (k == 4 || k == 22 || k == 32) {
            int s = (k == 4) ? 0 : (k == 22) ? 1 : 2;
#pragma unroll
            for (int p = 0; p < 9; p++) g_plane[s][p][idx] = t[8 - p];  // descending
            g_colsum[s][idx] = sum;
        }
    }
}

// ---------------------------------------------------------------------------
// Sorted merge of two sorted-descending 9-lists -> sorted-descending top-9.
// m[i] = max(A[i], B[8-i]) is the top-9 multiset and is V-shaped (bitonic);
// the 13-CE network below sorts it (derived from padded bitonic-16 with
// constant folding; verified on asc/desc/V inputs).
// ---------------------------------------------------------------------------
__device__ __forceinline__ void ced(float& x, float& y) {
    float hi = fmaxf(x, y), lo = fminf(x, y);
    x = hi; y = lo;
}

__device__ __forceinline__ void merge9_sorted(const float* A, const float* B, float* O) {
    float v0 = fmaxf(A[0], B[8]);
    float v1 = fmaxf(A[1], B[7]);
    float v2 = fmaxf(A[2], B[6]);
    float v3 = fmaxf(A[3], B[5]);
    float v4 = fmaxf(A[4], B[4]);
    float v5 = fmaxf(A[5], B[3]);
    float v6 = fmaxf(A[6], B[2]);
    float v7 = fmaxf(A[7], B[1]);
    float v8 = fmaxf(A[8], B[0]);
    ced(v0, v8);
    ced(v1, v5); ced(v2, v6); ced(v3, v7); ced(v4, v8);
    ced(v1, v3); ced(v2, v4); ced(v5, v7); ced(v6, v8);
    ced(v1, v2); ced(v3, v4); ced(v5, v6); ced(v7, v8);
    O[0] = v0; O[1] = v1; O[2] = v2; O[3] = v3; O[4] = v4;
    O[5] = v5; O[6] = v6; O[7] = v7; O[8] = v8;
}

// Final (unsorted) merge: sum of the top-9 multiset of two sorted lists.
__device__ __forceinline__ float merge9_sum(const float* A, const float* B) {
    float s = fmaxf(A[0], B[8]);
    s += fmaxf(A[1], B[7]);
    s += fmaxf(A[2], B[6]);
    s += fmaxf(A[3], B[5]);
    s += fmaxf(A[4], B[4]);
    s += fmaxf(A[5], B[3]);
    s += fmaxf(A[6], B[2]);
    s += fmaxf(A[7], B[1]);
    s += fmaxf(A[8], B[0]);
    return s;
}

// ---------------------------------------------------------------------------
// K2: row merge via sparse-table levels. Lk[i] = top-9 of smem columns
// [i, i+2^k); window = disjoint power-of-2 decomposition:
//   S=33: L5[a] + L0[a+32];  S=23: L4[a]+L2[a+16]+L1[a+20]+L0[a+22];
//   S=5:  L2[a] + L0[a+4].
// Block = 128 pixels of one row, one scale (blockIdx.z).
// ---------------------------------------------------------------------------
#define RW 128
#define HALO 16
#define RC (RW + 2*HALO)   // 160

template <int S, int SC, int TOPL>
__device__ __forceinline__ void gw_scale(
    float (&sL)[6][RC][9], float (&sS)[6][RC],
    int row, int colbase, int tid)
{
    // Stage L0: per-plane coalesced global reads -> pixel-major smem
    // (stride 9: gcd(9,32)=1 -> conflict-free).
    {
        const float* cs = &g_colsum[SC][row * N];
        for (int i = tid; i < RC; i += RW)
            sS[0][i] = __ldg(&cs[refl(colbase - HALO + i)]);
#pragma unroll
        for (int p = 0; p < 9; p++) {
            const float* pl = &g_plane[SC][p][row * N];
            for (int i = tid; i < RC; i += RW)
                sL[0][i][p] = __ldg(&pl[refl(colbase - HALO + i)]);
        }
    }
    __syncthreads();

    // Build levels 1..TOPL: Lk[i] = merge(Lk-1[i], Lk-1[i+2^{k-1}]).
#pragma unroll
    for (int k = 1; k <= TOPL; k++) {
        const int d = 1 << (k - 1);
        const int lim = RC - (1 << k) + 1;
        for (int i = tid; i < lim; i += RW) {
            merge9_sorted(sL[k - 1][i], sL[k - 1][i + d], sL[k][i]);
            sS[k][i] = sS[k - 1][i] + sS[k - 1][i + d];
        }
        __syncthreads();
    }

    float sum9, wsum;
    if (S == 33) {
        int a = tid;                       // window start (halo 16, P=16)
        sum9 = merge9_sum(sL[5][a], sL[0][a + 32]);
        wsum = sS[5][a] + sS[0][a + 32];
    } else if (S == 23) {
        int a = tid + 5;                   // P=11
        float E[9], F[9];
        merge9_sorted(sL[4][a],      sL[2][a + 16], E);
        merge9_sorted(sL[1][a + 20], sL[0][a + 22], F);
        sum9 = merge9_sum(E, F);
        wsum = sS[4][a] + sS[2][a + 16] + sS[1][a + 20] + sS[0][a + 22];
    } else {
        int a = tid + 14;                  // P=2
        sum9 = merge9_sum(sL[2][a], sL[0][a + 4]);
        wsum = sS[2][a] + sS[0][a + 4];
    }

    float M = sum9 * (1.0f / 9.0f);
    float avg = wsum * (1.0f / (float)(S * S));
    int idx = row * N + colbase + tid;
    g_M[SC][idx] = M;
    g_IRIL[SC][idx] = M - avg;
}

__global__ __launch_bounds__(RW) void rowpass_all() {
    __shared__ float sL[6][RC][9];
    __shared__ float sS[6][RC];
    int row = blockIdx.y;
    int colbase = blockIdx.x * RW;
    int tid = threadIdx.x;

    if      (blockIdx.z == 0) gw_scale<5, 0, 2>(sL, sS, row, colbase, tid);
    else if (blockIdx.z == 1) gw_scale<23, 1, 4>(sL, sS, row, colbase, tid);
    else                      gw_scale<33, 2, 5>(sL, sS, row, colbase, tid);
}

// ---------------------------------------------------------------------------
// K3: fused combine (unchanged — measured-best direct-load form).
// ---------------------------------------------------------------------------
template <int D, int SC>
__device__ __forceinline__ float combine_one(int iy, int ix, float gg) {
    float BE = -FLT_MAX;
    float ni[9];
#pragma unroll
    for (int i = 0; i < 3; i++) {
        int yy = refl(iy + (i - 1) * D);
#pragma unroll
        for (int j = 0; j < 3; j++) {
            int xx = refl(ix + (j - 1) * D);
            int o = yy * N + xx;
            ni[i * 3 + j] = __ldg(&g_IRIL[SC][o]);
            if (!(i == 1 && j == 1)) BE = fmaxf(BE, __ldg(&g_M[SC][o]));
        }
    }

    float SLCM = fmaxf((BE / gg - 1.0f) * gg, 0.0f);

    float WT = ni[4];
    float mx = -FLT_MAX;
    float s = 0.0f;
#pragma unroll
    for (int k = 0; k < 9; k++) {
        if (k == 4) continue;
        mx = fmaxf(mx, ni[k]);
        s += ni[k];
    }
    float mean = s * 0.125f;
    float ss = 0.0f;
#pragma unroll
    for (int k = 0; k < 9; k++) {
        if (k == 4) continue;
        float d = ni[k] - mean;
        ss += d * d;
    }
    float WB = fmaxf(sqrtf(ss * (1.0f / 7.0f)), 5.0f);
    float WD = fmaxf(WT - mx, 0.0f);
    return SLCM * WT * WD / WB;
}

__global__ __launch_bounds__(256) void combine_all(const float* __restrict__ x,
                                                   float* __restrict__ out) {
    int idx = blockIdx.x * blockDim.x + threadIdx.x;
    if (idx >= NPIX) return;
    int iy = idx / N, ix = idx % N;

    const float kw[3] = {1.0f, 2.0f, 1.0f};
    float acc = 0.0f;
#pragma unroll
    for (int dy = -1; dy <= 1; dy++) {
        int yy = refl(iy + dy);
#pragma unroll
        for (int dx = -1; dx <= 1; dx++) {
            int xx = refl(ix + dx);
            acc += kw[dy + 1] * kw[dx + 1] * __ldg(&x[yy * N + xx]);
        }
    }
    float gg = acc * (255.0f / 16.0f) + 1.0f;

    float r = 0.0f;                                 // scale-3 branch is exactly 0
    r = fmaxf(r, combine_one<5, 0>(iy, ix, gg));
    r = fmaxf(r, combine_one<23, 1>(iy, ix, gg));
    r = fmaxf(r, combine_one<33, 2>(iy, ix, gg));
    out[idx] = r;
}

// ---------------------------------------------------------------------------
extern "C" void kernel_launch(void* const* d_in, const int* in_sizes, int n_in,
                              void* d_out, int out_size) {
    const float* x = (const float*)d_in[0];
    float* out = (float*)d_out;

    colpass_all<<<(NPIX + 255) / 256, 256>>>(x);

    dim3 rgrid(N / RW, N, 3);
    rowpass_all<<<rgrid, RW>>>();

    combine_all<<<(NPIX + 255) / 256, 256>>>(x, out);
}